// round 15
// baseline (speedup 1.0000x reference)
#include <cuda_runtime.h>
#include <cuda_fp16.h>
#include <mma.h>
#include <cstdint>

using namespace nvcuda;

#define NB 64       // N sequences per visual batch
#define LQ 77       // sequence length
#define DIM 768
#define NH 12
#define HD 64
#define VTOK 8
#define MB 8        // M visual batches
#define NLAYERS 12
#define BROWS (MB*NB)          // 512
#define ROWS (BROWS*LQ)        // 39424 (max; live packed rows ~16K)

// per-layer fp16 weight regions (halves)
#define S_IN  (2304*768)
#define S_OUT (768*768)
#define S_FC  (3072*768)
#define S_PJ  (768*3072)
#define W_OFF0 0
#define W_OFF1 (S_IN)
#define W_OFF2 (S_IN + S_OUT)
#define W_OFF3 (S_IN + S_OUT + S_FC)
#define W_TOT  (S_IN + S_OUT + S_FC + S_PJ)     // 7,077,888 halves = 14.2 MB
#define CVT_BLKS (W_TOT/4/256)                  // 6912 blocks of 256 (exact)
#define LNG 1024                                // grid-stride LN blocks

// ---- scratch (static device allocations; ~440MB total) ----
__device__ float  g_h[(size_t)ROWS*DIM];          // residual stream (fp32), packed rows
__device__ __half g_x16[(size_t)ROWS*DIM];        // LN out / attn out (fp16), packed
__device__ __half g_scr16[(size_t)ROWS*3072];     // qkv (2304) OR mlp hidden (3072), packed
__device__ __half g_wbuf[W_TOT];                  // per-layer fp16 weights (all 4 mats)
__device__ float  g_feats[BROWS*DIM];
__device__ int    g_pos[NB], g_eot[NB], g_len[NB];
__device__ int    g_off[BROWS+1];                 // packed row offset per sequence
__device__ int    g_meta[2];                      // [0]=P live rows, [1]=P padded to 128
__device__ int    g_rowb[ROWS];                   // packed row -> sequence id (or -1 pad)
__device__ int    g_rowl[ROWS];                   // packed row -> position in sequence

// ---------------------------------------------------------------------
__device__ __forceinline__ float blockReduceSum(float v) {
    __shared__ float red[32];
    int lane = threadIdx.x & 31, w = threadIdx.x >> 5;
    #pragma unroll
    for (int o = 16; o > 0; o >>= 1) v += __shfl_down_sync(0xffffffffu, v, o);
    if (lane == 0) red[w] = v;
    __syncthreads();
    int nw = (blockDim.x + 31) >> 5;
    v = (threadIdx.x < nw) ? red[threadIdx.x] : 0.f;
    if (w == 0) {
        #pragma unroll
        for (int o = 16; o > 0; o >>= 1) v += __shfl_down_sync(0xffffffffu, v, o);
        if (lane == 0) red[0] = v;
    }
    __syncthreads();
    float r = red[0];
    __syncthreads();
    return r;
}

// ---------------------------------------------------------------------
// find SOV/EOT per sequence; build packed offsets (rows beyond eot+7 are dead
// by causality: only row eot+V-1 feeds the output and attention is causal)
__global__ void find_tokens(const int* __restrict__ text) {
    int n = threadIdx.x;
    if (n < NB) {
        int p = -1, e = -1;
        for (int l = 0; l < LQ; l++) {
            int t = text[n*LQ + l];
            if (p < 0 && t == 49408) p = l;
            if (e < 0 && t == 49407) e = l;
        }
        g_pos[n] = p;
        g_eot[n] = e;
        g_len[n] = e + VTOK;          // eot + V - 1 + 1  (<= 77)
    }
    __syncthreads();
    if (n == 0) {
        int acc = 0;
        for (int b = 0; b < BROWS; b++) {
            g_off[b] = acc;
            acc += g_len[b & 63];
        }
        g_off[BROWS] = acc;
        g_meta[0] = acc;
        g_meta[1] = (acc + 127) & ~127;
    }
}

__global__ void init_map() {
    int i = blockIdx.x*blockDim.x + threadIdx.x;
    if (i < ROWS) g_rowb[i] = -1;
}

__global__ void fill_map() {
    int b = blockIdx.x;
    int n = b & 63;
    int o = g_off[b], L0 = g_len[n];
    for (int i = threadIdx.x; i < L0; i += blockDim.x) {
        g_rowb[o+i] = b;
        g_rowl[o+i] = i;
    }
}

// grid-stride over rows < g_meta[1] only (rows beyond are never read)
__global__ void embed_kernel(const int* __restrict__ text,
                             const float* __restrict__ vis,
                             const float* __restrict__ tok,
                             const float* __restrict__ pos) {
    const int nlive = g_meta[1];
    for (long p = blockIdx.x; p < nlive; p += gridDim.x) {
        int rb = g_rowb[p];
        float* dst = g_h + p*(long)DIM;
        if (rb < 0) {                 // pad row: zero (LN(0)=bias, finite)
            for (int d = threadIdx.x; d < DIM; d += blockDim.x) dst[d] = 0.f;
            continue;
        }
        int l = g_rowl[p];
        int m = rb >> 6;
        int n = rb & 63;
        int py = g_pos[n];
        const float* src;
        if (l >= py && l < py + VTOK) {
            src = vis + ((long)(m*VTOK + (l - py)))*DIM;
        } else {
            int sidx = (l < py) ? l : (l - VTOK + 1);
            sidx = min(max(sidx, 0), LQ-1);
            src = tok + (long)text[n*LQ + sidx]*DIM;
        }
        const float* pe = pos + (long)l*DIM;
        for (int d = threadIdx.x; d < DIM; d += blockDim.x)
            dst[d] = src[d] + pe[d];
    }
}

// ---------------------------------------------------------------------
// MERGED per-layer kernel: blocks [0, CVT_BLKS) convert this layer's 4 weight
// matrices fp32->fp16; blocks [CVT_BLKS, CVT_BLKS+LNG) do LN1 grid-stride.
// Both depend only on the previous layer's pj GEMM -> safe to run concurrently.
__global__ __launch_bounds__(256) void cvt_ln(const float4* __restrict__ inw,
                                              const float4* __restrict__ outw,
                                              const float4* __restrict__ fcw,
                                              const float4* __restrict__ pjw,
                                              const float* __restrict__ X,
                                              __half* __restrict__ Y,
                                              const float* __restrict__ lw,
                                              const float* __restrict__ lb) {
    const int tid = threadIdx.x;
    if (blockIdx.x < CVT_BLKS) {
        const int n4_0 = S_IN/4, n4_1 = S_OUT/4, n4_2 = S_FC/4;
        int i = blockIdx.x*256 + tid;
        const float4* s;
        __half2* d;
        int local;
        if (i < n4_0) {
            s = inw;  d = (__half2*)(g_wbuf + W_OFF0); local = i;
        } else if (i < n4_0 + n4_1) {
            s = outw; d = (__half2*)(g_wbuf + W_OFF1); local = i - n4_0;
        } else if (i < n4_0 + n4_1 + n4_2) {
            s = fcw;  d = (__half2*)(g_wbuf + W_OFF2); local = i - n4_0 - n4_1;
        } else {
            s = pjw;  d = (__half2*)(g_wbuf + W_OFF3); local = i - n4_0 - n4_1 - n4_2;
        }
        float4 v = s[local];
        d[local*2]   = __floats2half2_rn(v.x, v.y);
        d[local*2+1] = __floats2half2_rn(v.z, v.w);
    } else {
        const int nlive = g_meta[1];
        for (long row = blockIdx.x - CVT_BLKS; row < nlive; row += LNG) {
            const float* x = X + row*(long)DIM;
            float v[3];
            float s = 0.f;
            #pragma unroll
            for (int k = 0; k < 3; k++) { v[k] = x[tid + k*256]; s += v[k]; }
            float mean = blockReduceSum(s) * (1.f/DIM);
            float q = 0.f;
            #pragma unroll
            for (int k = 0; k < 3; k++) { float d0 = v[k]-mean; q += d0*d0; }
            float var = blockReduceSum(q) * (1.f/DIM);
            float rstd = rsqrtf(var + 1e-5f);
            #pragma unroll
            for (int k = 0; k < 3; k++) {
                int d = tid + k*256;
                Y[row*(long)DIM + d] = __float2half((v[k]-mean)*rstd*lw[d] + lb[d]);
            }
        }
    }
}

// LayerNorm row -> fp16; grid-stride over LIVE rows only (standalone, for ln2)
__global__ __launch_bounds__(256) void ln_kernel(const float* __restrict__ X,
                                                 __half* __restrict__ Y,
                                                 const float* __restrict__ w,
                                                 const float* __restrict__ b) {
    int tid = threadIdx.x;
    const int nlive = g_meta[1];
    for (long row = blockIdx.x; row < nlive; row += gridDim.x) {
        const float* x = X + row*(long)DIM;
        float v[3];
        float s = 0.f;
        #pragma unroll
        for (int k = 0; k < 3; k++) { v[k] = x[tid + k*256]; s += v[k]; }
        float mean = blockReduceSum(s) * (1.f/DIM);
        float q = 0.f;
        #pragma unroll
        for (int k = 0; k < 3; k++) { float d0 = v[k]-mean; q += d0*d0; }
        float var = blockReduceSum(q) * (1.f/DIM);
        float rstd = rsqrtf(var + 1e-5f);
        #pragma unroll
        for (int k = 0; k < 3; k++) {
            int d = tid + k*256;
            Y[row*(long)DIM + d] = __float2half((v[k]-mean)*rstd*w[d] + b[d]);
        }
    }
}

// ---------------------------------------------------------------------
// cp.async helpers
__device__ __forceinline__ void cpa16(void* smem, const void* gmem) {
    unsigned s = (unsigned)__cvta_generic_to_shared(smem);
    asm volatile("cp.async.cg.shared.global [%0], [%1], 16;\n" :: "r"(s), "l"(gmem));
}
#define CP_COMMIT() asm volatile("cp.async.commit_group;\n" ::: "memory")
#define CP_WAIT(n)  asm volatile("cp.async.wait_group %0;\n" :: "n"(n) : "memory")

// ---------------------------------------------------------------------
// NT GEMM (R9 mainloop): tile 128x128, BK=64, 3-stage, warp tile 64x32, 256 thr.
// EPI 2: Ch  = gelu(acc+bias) fp16
// EPI 3: Ch  = acc+bias       fp16
// EPI 4: split-K over blockIdx.z (2 splits): atomicAdd(C, acc + bias@z0)
#define BM 128
#define BN 128
#define BK 64
#define BSTR 72                        // 64 halves + 8 pad
#define T_STG (BM*BSTR)                // 9216 halves
#define OFF_B  (3*T_STG)
#define OFF_BIAS (6*T_STG*2)           // 110592 bytes
#define GSMEM_SZ (OFF_BIAS + BN*4)     // 111104 bytes

template<int EPI>
__global__ __launch_bounds__(256) void gemm_nt(const __half* __restrict__ A,
                                               const __half* __restrict__ B,
                                               const float* __restrict__ bias,
                                               float* __restrict__ C,
                                               __half* __restrict__ Ch,
                                               int N, int K) {
    const long bm = (long)blockIdx.y * BM;
    if (bm >= (long)g_meta[1]) return;          // dead tile (packed rows)
    extern __shared__ __half smh[];
    const int tid = threadIdx.x;
    const int warp = tid >> 5;
    const int lane = tid & 31;
    const long bn = (long)blockIdx.x * BN;
    const int wm = (warp >> 2) * 64;
    const int wn = (warp & 3) * 32;

    const int Keff = (EPI == 4) ? (K >> 1) : K;       // per-split K
    const long kbase = (EPI == 4) ? (long)blockIdx.z * Keff : 0;

    float* bias_s = (float*)((char*)smh + OFF_BIAS);
    if (tid < BN) bias_s[tid] = bias[bn + tid];

    wmma::fragment<wmma::accumulator,16,16,16,float> acc[4][2];
    #pragma unroll
    for (int i = 0; i < 4; i++)
        #pragma unroll
        for (int j = 0; j < 2; j++) wmma::fill_fragment(acc[i][j], 0.f);

    auto load_stage = [&](int slot, int k0) {
        __half* sA = smh + slot*T_STG;
        __half* sB = smh + OFF_B + slot*T_STG;
        #pragma unroll
        for (int i = 0; i < 4; i++) {
            int chunk = tid + i*256;
            int row = chunk >> 3;
            int col = (chunk & 7) * 8;
            cpa16(&sA[row*BSTR + col], &A[(bm+row)*(long)K + kbase + k0 + col]);
            cpa16(&sB[row*BSTR + col], &B[(bn+row)*(long)K + kbase + k0 + col]);
        }
        CP_COMMIT();
    };

    const int nt = Keff / BK;
    load_stage(0, 0);
    load_stage(1, BK);
    load_stage(2, 2*BK);

    for (int it = 0; it < nt; ++it) {
        int rem = nt - 1 - it;
        if (rem >= 2)      CP_WAIT(2);
        else if (rem == 1) CP_WAIT(1);
        else               CP_WAIT(0);
        __syncthreads();
        const int st = it % 3;
        const __half* sA = smh + st*T_STG;
        const __half* sB = smh + OFF_B + st*T_STG;
        #pragma unroll
        for (int kk = 0; kk < BK; kk += 16) {
            wmma::fragment<wmma::matrix_a,16,16,16,__half,wmma::row_major> af[4];
            wmma::fragment<wmma::matrix_b,16,16,16,__half,wmma::col_major> bf[2];
            #pragma unroll
            for (int i = 0; i < 4; i++) wmma::load_matrix_sync(af[i], sA + (wm+i*16)*BSTR + kk, BSTR);
            #pragma unroll
            for (int j = 0; j < 2; j++) wmma::load_matrix_sync(bf[j], sB + (wn+j*16)*BSTR + kk, BSTR);
            #pragma unroll
            for (int i = 0; i < 4; i++)
                #pragma unroll
                for (int j = 0; j < 2; j++)
                    wmma::mma_sync(acc[i][j], af[i], bf[j], acc[i][j]);
        }
        if (it + 3 < nt) {
            __syncthreads();
            load_stage(it % 3, (it+3)*BK);
        }
    }
    __syncthreads();

    float* cs = (float*)smh + warp*256;
    const bool addb = (EPI != 4) || (blockIdx.z == 0);
    #pragma unroll
    for (int i = 0; i < 4; i++)
        #pragma unroll
        for (int j = 0; j < 2; j++) {
            wmma::store_matrix_sync(cs, acc[i][j], 16, wmma::mem_row_major);
            __syncwarp();
            #pragma unroll
            for (int s = 0; s < 8; s++) {
                int e = lane + s*32;
                int r = e >> 4, c = e & 15;
                long grow = bm + wm + i*16 + r;
                int  tcol = wn + j*16 + c;
                float v = cs[e] + (addb ? bias_s[tcol] : 0.f);
                long idx = grow * (long)N + bn + tcol;
                if (EPI == 2) {
                    float g = v / (1.f + __expf(-1.702f * v));
                    Ch[idx] = __float2half(g);
                } else if (EPI == 3) {
                    Ch[idx] = __float2half(v);
                } else {
                    atomicAdd(&C[idx], v);
                }
            }
            __syncwarp();
        }
}

// ---------------------------------------------------------------------
// attention: one block per (seq, head); K/V staged as __half2 (20.6KB smem ->
// 10 blocks/SM), all math in fp32 via __half22float2.  Vectorized AV + store.
__global__ __launch_bounds__(128) void attn_kernel(const __half* __restrict__ qkv,
                                                   __half* __restrict__ o16) {
    __shared__ __half2 Ks[LQ][HD/2+1];   // 77 x 33 (odd stride: conflict-free)
    __shared__ __half2 Vs[LQ][HD/2+1];
    __shared__ float qs[4][HD];
    __shared__ float ps[4][96];
    int bh = blockIdx.x;
    int b = bh / NH, h = bh % NH;
    int n = b & 63;
    int tid = threadIdx.x, lane = tid & 31, w = tid >> 5;
    const float scale = 0.125f;
    const int Llen = g_len[n];
    const long rbase = (long)g_off[b];
    const long base  = rbase*2304 + h*64;         // even -> half2 aligned
    const __half2* qkv2 = (const __half2*)qkv;
    const long base2 = base >> 1;
    for (int idx = tid; idx < Llen*(HD/2); idx += 128) {
        int j = idx >> 5, d2 = idx & 31;
        Ks[j][d2] = qkv2[base2 + (long)j*1152 + 384 + d2];
        Vs[j][d2] = qkv2[base2 + (long)j*1152 + 768 + d2];
    }
    __syncthreads();

    for (int i = w; i < Llen; i += 4) {
        const __half* qrow = qkv + base + (long)i*2304;
        qs[w][lane]      = __half2float(qrow[lane]);
        qs[w][lane+32]   = __half2float(qrow[lane+32]);
        __syncwarp();
        float pl[3];
        float mx = -1e30f;
        #pragma unroll
        for (int t = 0; t < 3; t++) {
            int j = lane + t*32;
            float s = -1e30f;
            if (j <= i) {
                s = 0.f;
                #pragma unroll 8
                for (int d2 = 0; d2 < HD/2; d2++) {
                    float2 k2 = __half22float2(Ks[j][d2]);
                    s += qs[w][2*d2]*k2.x + qs[w][2*d2+1]*k2.y;
                }
                s *= scale;
            }
            pl[t] = s;
            mx = fmaxf(mx, s);
        }
        #pragma unroll
        for (int o = 16; o; o >>= 1) mx = fmaxf(mx, __shfl_xor_sync(0xffffffffu, mx, o));
        float sm = 0.f;
        #pragma unroll
        for (int t = 0; t < 3; t++) {
            int j = lane + t*32;
            float e = (j <= i) ? __expf(pl[t]-mx) : 0.f;
            pl[t] = e;
            sm += e;
        }
        #pragma unroll
        for (int o = 16; o; o >>= 1) sm += __shfl_xor_sync(0xffffffffu, sm, o);
        float sinv = 1.f / sm;
        ps[w][lane] = pl[0]; ps[w][lane+32] = pl[1]; ps[w][lane+64] = pl[2];
        __syncwarp();
        float ax = 0.f, ay = 0.f;                 // dims 2*lane, 2*lane+1
        for (int j = 0; j <= i; j++) {
            float pj = ps[w][j];
            float2 v2 = __half22float2(Vs[j][lane]);
            ax += pj*v2.x;
            ay += pj*v2.y;
        }
        __half2* orow2 = (__half2*)(o16 + (rbase + i)*DIM + h*HD);
        orow2[lane] = __floats2half2_rn(ax*sinv, ay*sinv);
        __syncwarp();
    }
}

// ---------------------------------------------------------------------
// final LN on EOT rows + NN matmul with text_proj; 8 sequences per block
__global__ __launch_bounds__(256) void final_proj(const float* __restrict__ H,
                                                  const float* __restrict__ lw,
                                                  const float* __restrict__ lb,
                                                  const float* __restrict__ TP,
                                                  float* __restrict__ F) {
    __shared__ float s[8][DIM];
    int i0 = blockIdx.x * 8;
    int tid = threadIdx.x;
    for (int r = 0; r < 8; r++) {
        int i = i0 + r;
        int n = i & 63;
        long row = (long)g_off[i] + g_len[n] - 1;   // packed row of eot+V-1
        const float* x = H + row*(long)DIM;
        float v[3];
        float ssum = 0.f;
        #pragma unroll
        for (int k = 0; k < 3; k++) { v[k] = x[tid + k*256]; ssum += v[k]; }
        float mean = blockReduceSum(ssum) * (1.f/DIM);
        float q = 0.f;
        #pragma unroll
        for (int k = 0; k < 3; k++) { float d0 = v[k]-mean; q += d0*d0; }
        float var = blockReduceSum(q) * (1.f/DIM);
        float rstd = rsqrtf(var + 1e-5f);
        #pragma unroll
        for (int k = 0; k < 3; k++) {
            int d = tid + k*256;
            s[r][d] = (v[k]-mean)*rstd*lw[d] + lb[d];
        }
    }
    __syncthreads();
    float acc[8][3];
    #pragma unroll
    for (int r = 0; r < 8; r++)
        #pragma unroll
        for (int k = 0; k < 3; k++) acc[r][k] = 0.f;
    for (int d = 0; d < DIM; d++) {
        float tp[3];
        #pragma unroll
        for (int k = 0; k < 3; k++) tp[k] = TP[(long)d*768 + tid + k*256];
        #pragma unroll
        for (int r = 0; r < 8; r++) {
            float sv = s[r][d];
            #pragma unroll
            for (int k = 0; k < 3; k++) acc[r][k] += sv * tp[k];
        }
    }
    #pragma unroll
    for (int r = 0; r < 8; r++)
        #pragma unroll
        for (int k = 0; k < 3; k++)
            F[(long)(i0+r)*768 + tid + k*256] = acc[r][k];
}

// normalize rows, mean over n (skip /64, cancels), normalize again
__global__ __launch_bounds__(256) void final_reduce(const float* __restrict__ F,
                                                    float* __restrict__ out) {
    int m = blockIdx.x, tid = threadIdx.x;
    float acc[3] = {0.f, 0.f, 0.f};
    for (int n = 0; n < NB; n++) {
        const float* f = F + ((long)(m*NB + n))*DIM;
        float v[3], ss = 0.f;
        #pragma unroll
        for (int k = 0; k < 3; k++) { v[k] = f[tid + k*256]; ss += v[k]*v[k]; }
        float tot = blockReduceSum(ss);
        float rn = rsqrtf(tot);
        #pragma unroll
        for (int k = 0; k < 3; k++) acc[k] += v[k]*rn;
    }
    float ss = 0.f;
    #pragma unroll
    for (int k = 0; k < 3; k++) ss += acc[k]*acc[k];
    float tot = blockReduceSum(ss);
    float rn = rsqrtf(tot);
    #pragma unroll
    for (int k = 0; k < 3; k++)
        out[(long)m*DIM + tid + k*256] = acc[k]*rn;
}

// ---------------------------------------------------------------------
extern "C" void kernel_launch(void* const* d_in, const int* in_sizes, int n_in,
                              void* d_out, int out_size) {
    const int*   text = (const int*)  d_in[0];
    const float* vis  = (const float*)d_in[1];
    const float* tok  = (const float*)d_in[2];
    const float* pos  = (const float*)d_in[3];
    const float* ln1w = (const float*)d_in[4];
    const float* ln1b = (const float*)d_in[5];
    const float* inw  = (const float*)d_in[6];
    const float* inb  = (const float*)d_in[7];
    const float* outw = (const float*)d_in[8];
    const float* outb = (const float*)d_in[9];
    const float* ln2w = (const float*)d_in[10];
    const float* ln2b = (const float*)d_in[11];
    const float* fcw  = (const float*)d_in[12];
    const float* fcb  = (const float*)d_in[13];
    const float* pjw  = (const float*)d_in[14];
    const float* pjb  = (const float*)d_in[15];
    const float* lnfw = (const float*)d_in[16];
    const float* lnfb = (const float*)d_in[17];
    const float* tproj= (const float*)d_in[18];

    void* p;
    cudaGetSymbolAddress(&p, g_h);      float*  hbuf  = (float*)p;
    cudaGetSymbolAddress(&p, g_x16);    __half* x16   = (__half*)p;
    cudaGetSymbolAddress(&p, g_scr16);  __half* scr16 = (__half*)p;
    cudaGetSymbolAddress(&p, g_wbuf);   __half* wbuf  = (__half*)p;
    cudaGetSymbolAddress(&p, g_feats);  float*  feats = (float*)p;

    cudaFuncSetAttribute(gemm_nt<2>, cudaFuncAttributeMaxDynamicSharedMemorySize, GSMEM_SZ);
    cudaFuncSetAttribute(gemm_nt<3>, cudaFuncAttributeMaxDynamicSharedMemorySize, GSMEM_SZ);
    cudaFuncSetAttribute(gemm_nt<4>, cudaFuncAttributeMaxDynamicSharedMemorySize, GSMEM_SZ);

    find_tokens<<<1, 64>>>(text);
    init_map<<<(ROWS+255)/256, 256>>>();
    fill_map<<<BROWS, 128>>>();
    embed_kernel<<<2048, 256>>>(text, vis, tok, pos);

    const int MT = ROWS / BM;        // 308 (static upper bound; dead tiles exit)
    for (int l = 0; l < NLAYERS; l++) {
        // merged: weight cvt (all 4 mats) + LN1, concurrent in one launch
        cvt_ln<<<CVT_BLKS + LNG, 256>>>((const float4*)(inw  + (long)l*S_IN),
                                        (const float4*)(outw + (long)l*S_OUT),
                                        (const float4*)(fcw  + (long)l*S_FC),
                                        (const float4*)(pjw  + (long)l*S_PJ),
                                        hbuf, x16, ln1w + l*DIM, ln1b + l*DIM);
        gemm_nt<3><<<dim3(2304/BN, MT), 256, GSMEM_SZ>>>(x16, wbuf + W_OFF0, inb + l*2304,
                                                         nullptr, scr16, 2304, 768);
        attn_kernel<<<BROWS*NH, 128>>>(scr16, x16);
        gemm_nt<4><<<dim3(768/BN, MT, 2), 256, GSMEM_SZ>>>(x16, wbuf + W_OFF1, outb + l*DIM,
                                                           hbuf, nullptr, 768, 768);
        // ---- MLP block ----
        ln_kernel<<<LNG, 256>>>(hbuf, x16, ln2w + l*DIM, ln2b + l*DIM);
        gemm_nt<2><<<dim3(3072/BN, MT), 256, GSMEM_SZ>>>(x16, wbuf + W_OFF2, fcb + l*3072,
                                                         nullptr, scr16, 3072, 768);
        gemm_nt<4><<<dim3(768/BN, MT, 2), 256, GSMEM_SZ>>>(scr16, wbuf + W_OFF3, pjb + l*DIM,
                                                           hbuf, nullptr, 768, 3072);
    }

    final_proj<<<BROWS/8, 256>>>(hbuf, lnfw, lnfb, tproj, feats);
    final_reduce<<<MB, 256>>>(feats, (float*)d_out);
}

// round 17
// speedup vs baseline: 1.4820x; 1.4820x over previous
#include <cuda_runtime.h>
#include <cuda_fp16.h>
#include <mma.h>
#include <cstdint>

using namespace nvcuda;

#define NB 64       // N sequences per visual batch
#define LQ 77       // sequence length
#define DIM 768
#define NH 12
#define HD 64
#define VTOK 8
#define MB 8        // M visual batches
#define NLAYERS 12
#define BROWS (MB*NB)          // 512
#define ROWS (BROWS*LQ)        // 39424 (max; live packed rows ~16K)

// per-layer fp16 weight regions (halves)
#define S_IN  (2304*768)
#define S_OUT (768*768)
#define S_FC  (3072*768)
#define S_PJ  (768*3072)
#define W_OFF0 0
#define W_OFF1 (S_IN)
#define W_OFF2 (S_IN + S_OUT)
#define W_OFF3 (S_IN + S_OUT + S_FC)
#define W_TOT  (S_IN + S_OUT + S_FC + S_PJ)     // 7,077,888 halves = 14.2 MB

// ---- scratch (static device allocations; ~440MB total) ----
__device__ float  g_h[(size_t)ROWS*DIM];          // residual stream (fp32), packed rows
__device__ __half g_x16[(size_t)ROWS*DIM];        // LN out / attn out (fp16), packed
__device__ __half g_scr16[(size_t)ROWS*3072];     // qkv (2304) OR mlp hidden (3072), packed
__device__ __half g_wbuf[W_TOT];                  // per-layer fp16 weights (all 4 mats)
__device__ float  g_feats[BROWS*DIM];
__device__ int    g_pos[NB], g_eot[NB], g_len[NB];
__device__ int    g_off[BROWS+1];                 // packed row offset per sequence
__device__ int    g_meta[2];                      // [0]=P live rows, [1]=P padded to 128
__device__ int    g_rowb[ROWS];                   // packed row -> sequence id (or -1 pad)
__device__ int    g_rowl[ROWS];                   // packed row -> position in sequence

// ---------------------------------------------------------------------
__device__ __forceinline__ float blockReduceSum(float v) {
    __shared__ float red[32];
    int lane = threadIdx.x & 31, w = threadIdx.x >> 5;
    #pragma unroll
    for (int o = 16; o > 0; o >>= 1) v += __shfl_down_sync(0xffffffffu, v, o);
    if (lane == 0) red[w] = v;
    __syncthreads();
    int nw = (blockDim.x + 31) >> 5;
    v = (threadIdx.x < nw) ? red[threadIdx.x] : 0.f;
    if (w == 0) {
        #pragma unroll
        for (int o = 16; o > 0; o >>= 1) v += __shfl_down_sync(0xffffffffu, v, o);
        if (lane == 0) red[0] = v;
    }
    __syncthreads();
    float r = red[0];
    __syncthreads();
    return r;
}

// ---------------------------------------------------------------------
// find SOV/EOT per sequence; build packed offsets (rows beyond eot+7 are dead
// by causality: only row eot+V-1 feeds the output and attention is causal)
__global__ void find_tokens(const int* __restrict__ text) {
    int n = threadIdx.x;
    if (n < NB) {
        int p = -1, e = -1;
        for (int l = 0; l < LQ; l++) {
            int t = text[n*LQ + l];
            if (p < 0 && t == 49408) p = l;
            if (e < 0 && t == 49407) e = l;
        }
        g_pos[n] = p;
        g_eot[n] = e;
        g_len[n] = e + VTOK;          // eot + V - 1 + 1  (<= 77)
    }
    __syncthreads();
    if (n == 0) {
        int acc = 0;
        for (int b = 0; b < BROWS; b++) {
            g_off[b] = acc;
            acc += g_len[b & 63];
        }
        g_off[BROWS] = acc;
        g_meta[0] = acc;
        g_meta[1] = (acc + 127) & ~127;
    }
}

__global__ void init_map() {
    int i = blockIdx.x*blockDim.x + threadIdx.x;
    if (i < ROWS) g_rowb[i] = -1;
}

__global__ void fill_map() {
    int b = blockIdx.x;
    int n = b & 63;
    int o = g_off[b], L0 = g_len[n];
    for (int i = threadIdx.x; i < L0; i += blockDim.x) {
        g_rowb[o+i] = b;
        g_rowl[o+i] = i;
    }
}

// grid-stride over rows < g_meta[1] only (rows beyond are never read)
__global__ void embed_kernel(const int* __restrict__ text,
                             const float* __restrict__ vis,
                             const float* __restrict__ tok,
                             const float* __restrict__ pos) {
    const int nlive = g_meta[1];
    for (long p = blockIdx.x; p < nlive; p += gridDim.x) {
        int rb = g_rowb[p];
        float* dst = g_h + p*(long)DIM;
        if (rb < 0) {                 // pad row: zero (LN(0)=bias, finite)
            for (int d = threadIdx.x; d < DIM; d += blockDim.x) dst[d] = 0.f;
            continue;
        }
        int l = g_rowl[p];
        int m = rb >> 6;
        int n = rb & 63;
        int py = g_pos[n];
        const float* src;
        if (l >= py && l < py + VTOK) {
            src = vis + ((long)(m*VTOK + (l - py)))*DIM;
        } else {
            int sidx = (l < py) ? l : (l - VTOK + 1);
            sidx = min(max(sidx, 0), LQ-1);
            src = tok + (long)text[n*LQ + sidx]*DIM;
        }
        const float* pe = pos + (long)l*DIM;
        for (int d = threadIdx.x; d < DIM; d += blockDim.x)
            dst[d] = src[d] + pe[d];
    }
}

// batched fp32->fp16 weight convert: all 4 matrices of one layer, one launch.
__global__ void cvt_layer(const float4* __restrict__ inw,
                          const float4* __restrict__ outw,
                          const float4* __restrict__ fcw,
                          const float4* __restrict__ pjw) {
    const int n4_0 = S_IN/4, n4_1 = S_OUT/4, n4_2 = S_FC/4, n4_3 = S_PJ/4;
    int i = blockIdx.x*blockDim.x + threadIdx.x;
    const float4* s;
    __half2* d;
    int local;
    if (i < n4_0) {
        s = inw;  d = (__half2*)(g_wbuf + W_OFF0); local = i;
    } else if (i < n4_0 + n4_1) {
        s = outw; d = (__half2*)(g_wbuf + W_OFF1); local = i - n4_0;
    } else if (i < n4_0 + n4_1 + n4_2) {
        s = fcw;  d = (__half2*)(g_wbuf + W_OFF2); local = i - n4_0 - n4_1;
    } else if (i < n4_0 + n4_1 + n4_2 + n4_3) {
        s = pjw;  d = (__half2*)(g_wbuf + W_OFF3); local = i - n4_0 - n4_1 - n4_2;
    } else {
        return;
    }
    float4 v = s[local];
    d[local*2]   = __floats2half2_rn(v.x, v.y);
    d[local*2+1] = __floats2half2_rn(v.z, v.w);
}

// LayerNorm row -> fp16; grid-stride over LIVE rows only (g_meta[1])
__global__ __launch_bounds__(256) void ln_kernel(const float* __restrict__ X,
                                                 __half* __restrict__ Y,
                                                 const float* __restrict__ w,
                                                 const float* __restrict__ b) {
    int tid = threadIdx.x;
    const int nlive = g_meta[1];
    for (long row = blockIdx.x; row < nlive; row += gridDim.x) {
        const float* x = X + row*(long)DIM;
        float v[3];
        float s = 0.f;
        #pragma unroll
        for (int k = 0; k < 3; k++) { v[k] = x[tid + k*256]; s += v[k]; }
        float mean = blockReduceSum(s) * (1.f/DIM);
        float q = 0.f;
        #pragma unroll
        for (int k = 0; k < 3; k++) { float d0 = v[k]-mean; q += d0*d0; }
        float var = blockReduceSum(q) * (1.f/DIM);
        float rstd = rsqrtf(var + 1e-5f);
        #pragma unroll
        for (int k = 0; k < 3; k++) {
            int d = tid + k*256;
            Y[row*(long)DIM + d] = __float2half((v[k]-mean)*rstd*w[d] + b[d]);
        }
    }
}

// ---------------------------------------------------------------------
// cp.async helpers
__device__ __forceinline__ void cpa16(void* smem, const void* gmem) {
    unsigned s = (unsigned)__cvta_generic_to_shared(smem);
    asm volatile("cp.async.cg.shared.global [%0], [%1], 16;\n" :: "r"(s), "l"(gmem));
}
#define CP_COMMIT() asm volatile("cp.async.commit_group;\n" ::: "memory")
#define CP_WAIT(n)  asm volatile("cp.async.wait_group %0;\n" :: "n"(n) : "memory")

// ---------------------------------------------------------------------
// NT GEMM (R9 mainloop): tile 128x128, BK=64, 3-stage, warp tile 64x32, 256 thr.
// EPI 2: Ch  = gelu(acc+bias) fp16
// EPI 3: Ch  = acc+bias       fp16
// EPI 4: split-K over blockIdx.z (2 splits): atomicAdd(C, acc + bias@z0)
#define BM 128
#define BN 128
#define BK 64
#define BSTR 72                        // 64 halves + 8 pad
#define T_STG (BM*BSTR)                // 9216 halves
#define OFF_B  (3*T_STG)
#define OFF_BIAS (6*T_STG*2)           // 110592 bytes
#define GSMEM_SZ (OFF_BIAS + BN*4)     // 111104 bytes

template<int EPI>
__global__ __launch_bounds__(256) void gemm_nt(const __half* __restrict__ A,
                                               const __half* __restrict__ B,
                                               const float* __restrict__ bias,
                                               float* __restrict__ C,
                                               __half* __restrict__ Ch,
                                               int N, int K) {
    const long bm = (long)blockIdx.y * BM;
    if (bm >= (long)g_meta[1]) return;          // dead tile (packed rows)
    extern __shared__ __half smh[];
    const int tid = threadIdx.x;
    const int warp = tid >> 5;
    const int lane = tid & 31;
    const long bn = (long)blockIdx.x * BN;
    const int wm = (warp >> 2) * 64;
    const int wn = (warp & 3) * 32;

    const int Keff = (EPI == 4) ? (K >> 1) : K;       // per-split K
    const long kbase = (EPI == 4) ? (long)blockIdx.z * Keff : 0;

    float* bias_s = (float*)((char*)smh + OFF_BIAS);
    if (tid < BN) bias_s[tid] = bias[bn + tid];

    wmma::fragment<wmma::accumulator,16,16,16,float> acc[4][2];
    #pragma unroll
    for (int i = 0; i < 4; i++)
        #pragma unroll
        for (int j = 0; j < 2; j++) wmma::fill_fragment(acc[i][j], 0.f);

    auto load_stage = [&](int slot, int k0) {
        __half* sA = smh + slot*T_STG;
        __half* sB = smh + OFF_B + slot*T_STG;
        #pragma unroll
        for (int i = 0; i < 4; i++) {
            int chunk = tid + i*256;
            int row = chunk >> 3;
            int col = (chunk & 7) * 8;
            cpa16(&sA[row*BSTR + col], &A[(bm+row)*(long)K + kbase + k0 + col]);
            cpa16(&sB[row*BSTR + col], &B[(bn+row)*(long)K + kbase + k0 + col]);
        }
        CP_COMMIT();
    };

    const int nt = Keff / BK;
    load_stage(0, 0);
    load_stage(1, BK);
    load_stage(2, 2*BK);

    for (int it = 0; it < nt; ++it) {
        int rem = nt - 1 - it;
        if (rem >= 2)      CP_WAIT(2);
        else if (rem == 1) CP_WAIT(1);
        else               CP_WAIT(0);
        __syncthreads();
        const int st = it % 3;
        const __half* sA = smh + st*T_STG;
        const __half* sB = smh + OFF_B + st*T_STG;
        #pragma unroll
        for (int kk = 0; kk < BK; kk += 16) {
            wmma::fragment<wmma::matrix_a,16,16,16,__half,wmma::row_major> af[4];
            wmma::fragment<wmma::matrix_b,16,16,16,__half,wmma::col_major> bf[2];
            #pragma unroll
            for (int i = 0; i < 4; i++) wmma::load_matrix_sync(af[i], sA + (wm+i*16)*BSTR + kk, BSTR);
            #pragma unroll
            for (int j = 0; j < 2; j++) wmma::load_matrix_sync(bf[j], sB + (wn+j*16)*BSTR + kk, BSTR);
            #pragma unroll
            for (int i = 0; i < 4; i++)
                #pragma unroll
                for (int j = 0; j < 2; j++)
                    wmma::mma_sync(acc[i][j], af[i], bf[j], acc[i][j]);
        }
        if (it + 3 < nt) {
            __syncthreads();
            load_stage(it % 3, (it+3)*BK);
        }
    }
    __syncthreads();

    float* cs = (float*)smh + warp*256;
    const bool addb = (EPI != 4) || (blockIdx.z == 0);
    #pragma unroll
    for (int i = 0; i < 4; i++)
        #pragma unroll
        for (int j = 0; j < 2; j++) {
            wmma::store_matrix_sync(cs, acc[i][j], 16, wmma::mem_row_major);
            __syncwarp();
            #pragma unroll
            for (int s = 0; s < 8; s++) {
                int e = lane + s*32;
                int r = e >> 4, c = e & 15;
                long grow = bm + wm + i*16 + r;
                int  tcol = wn + j*16 + c;
                float v = cs[e] + (addb ? bias_s[tcol] : 0.f);
                long idx = grow * (long)N + bn + tcol;
                if (EPI == 2) {
                    float g = v / (1.f + __expf(-1.702f * v));
                    Ch[idx] = __float2half(g);
                } else if (EPI == 3) {
                    Ch[idx] = __float2half(v);
                } else {
                    atomicAdd(&C[idx], v);
                }
            }
            __syncwarp();
        }
}

// ---------------------------------------------------------------------
// attention: one block per (seq, head); packed rows, per-sequence length
__global__ __launch_bounds__(128) void attn_kernel(const __half* __restrict__ qkv,
                                                   __half* __restrict__ o16) {
    __shared__ float Ks[LQ][HD+1];
    __shared__ float Vs[LQ][HD+1];
    __shared__ float qs[4][HD];
    __shared__ float ps[4][96];
    int bh = blockIdx.x;
    int b = bh / NH, h = bh % NH;
    int n = b & 63;
    int tid = threadIdx.x, lane = tid & 31, w = tid >> 5;
    const float scale = 0.125f;
    const int Llen = g_len[n];
    const long rbase = (long)g_off[b];
    long base = rbase*2304 + h*64;
    for (int idx = tid; idx < Llen*HD; idx += 128) {
        int j = idx >> 6, d = idx & 63;
        Ks[j][d] = __half2float(qkv[base + (long)j*2304 + 768  + d]);
        Vs[j][d] = __half2float(qkv[base + (long)j*2304 + 1536 + d]);
    }
    __syncthreads();

    for (int i = w; i < Llen; i += 4) {
        const __half* qrow = qkv + base + (long)i*2304;
        qs[w][lane]      = __half2float(qrow[lane]);
        qs[w][lane+32]   = __half2float(qrow[lane+32]);
        __syncwarp();
        float pl[3];
        float mx = -1e30f;
        #pragma unroll
        for (int t = 0; t < 3; t++) {
            int j = lane + t*32;
            float s = -1e30f;
            if (j <= i) {
                s = 0.f;
                #pragma unroll 16
                for (int d = 0; d < HD; d++) s += qs[w][d]*Ks[j][d];
                s *= scale;
            }
            pl[t] = s;
            mx = fmaxf(mx, s);
        }
        #pragma unroll
        for (int o = 16; o; o >>= 1) mx = fmaxf(mx, __shfl_xor_sync(0xffffffffu, mx, o));
        float sm = 0.f;
        #pragma unroll
        for (int t = 0; t < 3; t++) {
            int j = lane + t*32;
            float e = (j <= i) ? __expf(pl[t]-mx) : 0.f;
            pl[t] = e;
            sm += e;
        }
        #pragma unroll
        for (int o = 16; o; o >>= 1) sm += __shfl_xor_sync(0xffffffffu, sm, o);
        float sinv = 1.f / sm;
        ps[w][lane] = pl[0]; ps[w][lane+32] = pl[1]; ps[w][lane+64] = pl[2];
        __syncwarp();
        float a0 = 0.f, a1 = 0.f;
        for (int j = 0; j <= i; j++) {
            float pj = ps[w][j];
            a0 += pj*Vs[j][lane];
            a1 += pj*Vs[j][lane+32];
        }
        __half* orow = o16 + (rbase + i)*DIM + h*HD;
        orow[lane]    = __float2half(a0*sinv);
        orow[lane+32] = __float2half(a1*sinv);
        __syncwarp();
    }
}

// ---------------------------------------------------------------------
// final LN on EOT rows + NN matmul with text_proj; 8 sequences per block
__global__ __launch_bounds__(256) void final_proj(const float* __restrict__ H,
                                                  const float* __restrict__ lw,
                                                  const float* __restrict__ lb,
                                                  const float* __restrict__ TP,
                                                  float* __restrict__ F) {
    __shared__ float s[8][DIM];
    int i0 = blockIdx.x * 8;
    int tid = threadIdx.x;
    for (int r = 0; r < 8; r++) {
        int i = i0 + r;
        int n = i & 63;
        long row = (long)g_off[i] + g_len[n] - 1;   // packed row of eot+V-1
        const float* x = H + row*(long)DIM;
        float v[3];
        float ssum = 0.f;
        #pragma unroll
        for (int k = 0; k < 3; k++) { v[k] = x[tid + k*256]; ssum += v[k]; }
        float mean = blockReduceSum(ssum) * (1.f/DIM);
        float q = 0.f;
        #pragma unroll
        for (int k = 0; k < 3; k++) { float d0 = v[k]-mean; q += d0*d0; }
        float var = blockReduceSum(q) * (1.f/DIM);
        float rstd = rsqrtf(var + 1e-5f);
        #pragma unroll
        for (int k = 0; k < 3; k++) {
            int d = tid + k*256;
            s[r][d] = (v[k]-mean)*rstd*lw[d] + lb[d];
        }
    }
    __syncthreads();
    float acc[8][3];
    #pragma unroll
    for (int r = 0; r < 8; r++)
        #pragma unroll
        for (int k = 0; k < 3; k++) acc[r][k] = 0.f;
    for (int d = 0; d < DIM; d++) {
        float tp[3];
        #pragma unroll
        for (int k = 0; k < 3; k++) tp[k] = TP[(long)d*768 + tid + k*256];
        #pragma unroll
        for (int r = 0; r < 8; r++) {
            float sv = s[r][d];
            #pragma unroll
            for (int k = 0; k < 3; k++) acc[r][k] += sv * tp[k];
        }
    }
    #pragma unroll
    for (int r = 0; r < 8; r++)
        #pragma unroll
        for (int k = 0; k < 3; k++)
            F[(long)(i0+r)*768 + tid + k*256] = acc[r][k];
}

// normalize rows, mean over n (skip /64, cancels), normalize again
__global__ __launch_bounds__(256) void final_reduce(const float* __restrict__ F,
                                                    float* __restrict__ out) {
    int m = blockIdx.x, tid = threadIdx.x;
    float acc[3] = {0.f, 0.f, 0.f};
    for (int n = 0; n < NB; n++) {
        const float* f = F + ((long)(m*NB + n))*DIM;
        float v[3], ss = 0.f;
        #pragma unroll
        for (int k = 0; k < 3; k++) { v[k] = f[tid + k*256]; ss += v[k]*v[k]; }
        float tot = blockReduceSum(ss);
        float rn = rsqrtf(tot);
        #pragma unroll
        for (int k = 0; k < 3; k++) acc[k] += v[k]*rn;
    }
    float ss = 0.f;
    #pragma unroll
    for (int k = 0; k < 3; k++) ss += acc[k]*acc[k];
    float tot = blockReduceSum(ss);
    float rn = rsqrtf(tot);
    #pragma unroll
    for (int k = 0; k < 3; k++)
        out[(long)m*DIM + tid + k*256] = acc[k]*rn;
}

// ---------------------------------------------------------------------
extern "C" void kernel_launch(void* const* d_in, const int* in_sizes, int n_in,
                              void* d_out, int out_size) {
    const int*   text = (const int*)  d_in[0];
    const float* vis  = (const float*)d_in[1];
    const float* tok  = (const float*)d_in[2];
    const float* pos  = (const float*)d_in[3];
    const float* ln1w = (const float*)d_in[4];
    const float* ln1b = (const float*)d_in[5];
    const float* inw  = (const float*)d_in[6];
    const float* inb  = (const float*)d_in[7];
    const float* outw = (const float*)d_in[8];
    const float* outb = (const float*)d_in[9];
    const float* ln2w = (const float*)d_in[10];
    const float* ln2b = (const float*)d_in[11];
    const float* fcw  = (const float*)d_in[12];
    const float* fcb  = (const float*)d_in[13];
    const float* pjw  = (const float*)d_in[14];
    const float* pjb  = (const float*)d_in[15];
    const float* lnfw = (const float*)d_in[16];
    const float* lnfb = (const float*)d_in[17];
    const float* tproj= (const float*)d_in[18];

    void* p;
    cudaGetSymbolAddress(&p, g_h);      float*  hbuf  = (float*)p;
    cudaGetSymbolAddress(&p, g_x16);    __half* x16   = (__half*)p;
    cudaGetSymbolAddress(&p, g_scr16);  __half* scr16 = (__half*)p;
    cudaGetSymbolAddress(&p, g_wbuf);   __half* wbuf  = (__half*)p;
    cudaGetSymbolAddress(&p, g_feats);  float*  feats = (float*)p;

    cudaFuncSetAttribute(gemm_nt<2>, cudaFuncAttributeMaxDynamicSharedMemorySize, GSMEM_SZ);
    cudaFuncSetAttribute(gemm_nt<3>, cudaFuncAttributeMaxDynamicSharedMemorySize, GSMEM_SZ);
    cudaFuncSetAttribute(gemm_nt<4>, cudaFuncAttributeMaxDynamicSharedMemorySize, GSMEM_SZ);

    find_tokens<<<1, 64>>>(text);
    init_map<<<(ROWS+255)/256, 256>>>();
    fill_map<<<BROWS, 128>>>();
    embed_kernel<<<4096, 256>>>(text, vis, tok, pos);

    const int MT = ROWS / BM;        // 308 (static upper bound; dead tiles exit)
    const int LNG = 2048;            // grid-stride LN blocks (~8 rows/block)
    const int CVT_BLKS = (W_TOT/4 + 255) / 256;   // one batched cvt per layer
    for (int l = 0; l < NLAYERS; l++) {
        cvt_layer<<<CVT_BLKS, 256>>>((const float4*)(inw  + (long)l*S_IN),
                                     (const float4*)(outw + (long)l*S_OUT),
                                     (const float4*)(fcw  + (long)l*S_FC),
                                     (const float4*)(pjw  + (long)l*S_PJ));
        // ---- attention block ----
        ln_kernel<<<LNG, 256>>>(hbuf, x16, ln1w + l*DIM, ln1b + l*DIM);
        gemm_nt<3><<<dim3(2304/BN, MT), 256, GSMEM_SZ>>>(x16, wbuf + W_OFF0, inb + l*2304,
                                                         nullptr, scr16, 2304, 768);
        attn_kernel<<<BROWS*NH, 128>>>(scr16, x16);
        gemm_nt<4><<<dim3(768/BN, MT, 2), 256, GSMEM_SZ>>>(x16, wbuf + W_OFF1, outb + l*DIM,
                                                           hbuf, nullptr, 768, 768);
        // ---- MLP block ----
        ln_kernel<<<LNG, 256>>>(hbuf, x16, ln2w + l*DIM, ln2b + l*DIM);
        gemm_nt<2><<<dim3(3072/BN, MT), 256, GSMEM_SZ>>>(x16, wbuf + W_OFF2, fcb + l*3072,
                                                         nullptr, scr16, 3072, 768);
        gemm_nt<4><<<dim3(768/BN, MT, 2), 256, GSMEM_SZ>>>(scr16, wbuf + W_OFF3, pjb + l*DIM,
                                                           hbuf, nullptr, 768, 3072);
    }

    final_proj<<<BROWS/8, 256>>>(hbuf, lnfw, lnfb, tproj, feats);
    final_reduce<<<MB, 256>>>(feats, (float*)d_out);
}